// round 14
// baseline (speedup 1.0000x reference)
#include <cuda_runtime.h>
#include <cuda_bf16.h>
#include <cstdint>
#include <math.h>

#define DIM 128
#define FFN 512
#define KNN 9
#define TPB 256
#define RT  64       // rows per CTA tile (M)
#define NMAX 50000

#define SA 136       // bf16 smem tile row stride (128 + 8 pad, conflict-free ldmatrix)
#define RSTR 132     // resid smem row stride (floats)
#define ASZ (RT * SA)            // 8704 elems
#define BSZ (128 * SA)           // 17408 elems
#define FS_BYTES ((2 * ASZ + 2 * BSZ) * 2)             // 104448
#define MSG1_BYTES (FS_BYTES + (RT * KNN + 2) * 4)

// ====================== scalar helpers ====================================
__device__ __forceinline__ float gelu_exact(float v) {
    return 0.5f * v * (1.0f + erff(v * 0.70710678118654752f));
}
__device__ __forceinline__ uint32_t pbf(float a, float b) {
    uint16_t ua = __bfloat16_as_ushort(__float2bfloat16(a));
    uint16_t ub = __bfloat16_as_ushort(__float2bfloat16(b));
    return (uint32_t)ua | ((uint32_t)ub << 16);
}
__device__ __forceinline__ float bf_hi(float v) {
    return __bfloat162float(__float2bfloat16(v));
}

// ====================== HMMA / cp.async helpers (compute_100-safe) ========
__device__ __forceinline__ uint32_t s2u(const void* p) {
    uint32_t a;
    asm("{ .reg .u64 t; cvta.to.shared.u64 t, %1; cvt.u32.u64 %0, t; }"
        : "=r"(a) : "l"(p));
    return a;
}
__device__ __forceinline__ void ldsm4(uint32_t* r, uint32_t addr) {
    asm volatile("ldmatrix.sync.aligned.m8n8.x4.shared.b16 {%0,%1,%2,%3}, [%4];"
        : "=r"(r[0]), "=r"(r[1]), "=r"(r[2]), "=r"(r[3]) : "r"(addr));
}
__device__ __forceinline__ void mma_bf16(float* c, const uint32_t* a,
                                         uint32_t b0, uint32_t b1) {
    asm volatile(
        "mma.sync.aligned.m16n8k16.row.col.f32.bf16.bf16.f32 "
        "{%0,%1,%2,%3}, {%4,%5,%6,%7}, {%8,%9}, {%0,%1,%2,%3};"
        : "+f"(c[0]), "+f"(c[1]), "+f"(c[2]), "+f"(c[3])
        : "r"(a[0]), "r"(a[1]), "r"(a[2]), "r"(a[3]), "r"(b0), "r"(b1));
}
__device__ __forceinline__ void cpa16(uint32_t dst, const void* src, int srcsz) {
    asm volatile("cp.async.cg.shared.global [%0], [%1], 16, %2;"
        :: "r"(dst), "l"(src), "r"(srcsz));
}
__device__ __forceinline__ void cpa_wait() {
    asm volatile("cp.async.commit_group;\ncp.async.wait_group 0;" ::: "memory");
}

// ====================== scratch (no allocations anywhere) =================
__device__ float g_h [(size_t)NMAX * DIM];
__device__ float g_x1[(size_t)NMAX * DIM];
__device__ __align__(256) __nv_bfloat16 g_hh [(size_t)NMAX * DIM];
__device__ __align__(256) __nv_bfloat16 g_hl [(size_t)NMAX * DIM];
__device__ __align__(256) __nv_bfloat16 g_h2h[(size_t)NMAX * DIM];
__device__ __align__(256) __nv_bfloat16 g_h2l[(size_t)NMAX * DIM];
__device__ __align__(256) __nv_bfloat16 g_x1h[(size_t)NMAX * DIM];
__device__ __align__(256) __nv_bfloat16 g_x1l[(size_t)NMAX * DIM];
__device__ __align__(256) __nv_bfloat16 g_th [(size_t)NMAX * FFN];
__device__ __align__(256) __nv_bfloat16 g_tl [(size_t)NMAX * FFN];
__device__ __align__(256) __nv_bfloat16 g_wih[DIM * DIM], g_wil[DIM * DIM];   // W_in^T  [128n,128k]
__device__ __align__(256) __nv_bfloat16 g_wuh[DIM * 256], g_wul[DIM * 256];   // W_upd^T [128n,256k]
__device__ __align__(256) __nv_bfloat16 g_woh[DIM * DIM], g_wol[DIM * DIM];   // W_out^T [128n,128k]
__device__ __align__(256) __nv_bfloat16 g_w1h[FFN * DIM], g_w1l[FFN * DIM];   // ffn1^T  [512n,128k]
__device__ __align__(256) __nv_bfloat16 g_w2h[DIM * FFN], g_w2l[DIM * FFN];   // ffn2^T  [128n,512k]

// ====================== staging ===========================================
// bf16 src -> smem tile [nrows x 128 k] via cp.async (row stride SA).
__device__ __forceinline__ void stage_t(uint32_t dst,
        const __nv_bfloat16* __restrict__ src, int ldk, int k0,
        int row0, int nrows, int nvalid, int tid) {
    for (int i = tid; i < nrows * 16; i += TPB) {
        int row = i >> 4, ch = i & 15;
        int gr = row0 + row;
        int sz = (gr < nvalid) ? 16 : 0;
        int gs = min(gr, nvalid - 1);
        cpa16(dst + (uint32_t)((row * SA + ch * 8) * 2),
              src + (size_t)gs * ldk + k0 + ch * 8, sz);
    }
}

// fp32 src -> split hi/lo smem tiles (register path)
__device__ __forceinline__ void stage_s(__nv_bfloat16* Ah, __nv_bfloat16* Al,
        const float* __restrict__ src, int ldk, int row0, int nrows,
        int nvalid, int tid) {
    for (int i = tid; i < nrows * 16; i += TPB) {
        int row = i >> 4, ch = i & 15;
        float4 v0 = make_float4(0.f, 0.f, 0.f, 0.f), v1 = v0;
        int gr = row0 + row;
        if (gr < nvalid) {
            const float* s = src + (size_t)gr * ldk + ch * 8;
            v0 = *(const float4*)s;
            v1 = *(const float4*)(s + 4);
        }
        uint4 hh, ll;
        hh.x = pbf(v0.x, v0.y); hh.y = pbf(v0.z, v0.w);
        hh.z = pbf(v1.x, v1.y); hh.w = pbf(v1.z, v1.w);
        ll.x = pbf(v0.x - bf_hi(v0.x), v0.y - bf_hi(v0.y));
        ll.y = pbf(v0.z - bf_hi(v0.z), v0.w - bf_hi(v0.w));
        ll.z = pbf(v1.x - bf_hi(v1.x), v1.y - bf_hi(v1.y));
        ll.w = pbf(v1.z - bf_hi(v1.z), v1.w - bf_hi(v1.w));
        *(uint4*)(Ah + row * SA + ch * 8) = hh;
        *(uint4*)(Al + row * SA + ch * 8) = ll;
    }
}

// ====================== core warp-tile MMA (32x32 slice) ==================
__device__ __forceinline__ void mma_tile(uint32_t sA, uint32_t sB,
        int lane, int mw, int nw, float C[2][4][4]) {
    uint32_t aB = sA + (uint32_t)(((mw + (lane & 15)) * SA + (lane >> 4) * 8) * 2);
    uint32_t bB = sB + (uint32_t)(((nw + ((lane >> 4) << 3) + (lane & 7)) * SA
                                   + (((lane >> 3) & 1) << 3)) * 2);
    #pragma unroll
    for (int k = 0; k < 8; k++) {
        uint32_t a0[4], a1[4];
        ldsm4(a0, aB + k * 32);
        ldsm4(a1, aB + 16 * SA * 2 + k * 32);
        #pragma unroll
        for (int nj = 0; nj < 2; nj++) {
            uint32_t b[4];
            ldsm4(b, bB + nj * (16 * SA * 2) + k * 32);
            mma_bf16(C[0][nj * 2],     a0, b[0], b[1]);
            mma_bf16(C[0][nj * 2 + 1], a0, b[2], b[3]);
            mma_bf16(C[1][nj * 2],     a1, b[0], b[1]);
            mma_bf16(C[1][nj * 2 + 1], a1, b[2], b[3]);
        }
    }
}
#define C_ZERO(C)                                   \
    _Pragma("unroll")                               \
    for (int a_ = 0; a_ < 2; a_++)                  \
        _Pragma("unroll")                           \
        for (int b_ = 0; b_ < 4; b_++)              \
            _Pragma("unroll")                       \
            for (int c_ = 0; c_ < 4; c_++) C[a_][b_][c_] = 0.f;

__device__ __forceinline__ void mma_split(uint32_t sAh, uint32_t sAl,
        uint32_t sBh, uint32_t sBl, int lane, int mw, int nw, float C[2][4][4]) {
    mma_tile(sAh, sBh, lane, mw, nw, C);
    mma_tile(sAh, sBl, lane, mw, nw, C);
    mma_tile(sAl, sBh, lane, mw, nw, C);
}

// LN over RT rows of resid (stride rstr); emits fp32 + bf16 hi/lo split.
__device__ __forceinline__ void ln_rows_emit(const float* resid, int rstr,
        const float* __restrict__ gam, const float* __restrict__ bet,
        float* __restrict__ dstf, __nv_bfloat16* dsth, __nv_bfloat16* dstl,
        int row0, int n, int tid) {
    const int wid = tid >> 5, lane = tid & 31;
    const int d = lane * 4;
    float4 gv = *(const float4*)(gam + d);
    float4 bv = *(const float4*)(bet + d);
    for (int rl = wid; rl < RT; rl += 8) {
        int row = row0 + rl;
        if (row >= n) continue;
        float4 v = *(const float4*)(resid + rl * rstr + d);
        float s  = v.x + v.y + v.z + v.w;
        float sq = v.x * v.x + v.y * v.y + v.z * v.z + v.w * v.w;
        #pragma unroll
        for (int m = 16; m; m >>= 1) {
            s  += __shfl_xor_sync(0xffffffffu, s,  m);
            sq += __shfl_xor_sync(0xffffffffu, sq, m);
        }
        float mu = s * (1.f / DIM);
        float var = sq * (1.f / DIM) - mu * mu;
        float rs = rsqrtf(var + 1e-5f);
        float4 o;
        o.x = (v.x - mu) * rs * gv.x + bv.x;
        o.y = (v.y - mu) * rs * gv.y + bv.y;
        o.z = (v.z - mu) * rs * gv.z + bv.z;
        o.w = (v.w - mu) * rs * gv.w + bv.w;
        if (dstf) *(float4*)(dstf + (size_t)row * DIM + d) = o;
        uint2 hh, ll;
        hh.x = pbf(o.x, o.y);
        hh.y = pbf(o.z, o.w);
        ll.x = pbf(o.x - bf_hi(o.x), o.y - bf_hi(o.y));
        ll.y = pbf(o.z - bf_hi(o.z), o.w - bf_hi(o.w));
        *(uint2*)((uint16_t*)dsth + (size_t)row * DIM + d) = hh;
        *(uint2*)((uint16_t*)dstl + (size_t)row * DIM + d) = ll;
    }
}

// ====================== Kernel: weight convert/split ======================
__global__ __launch_bounds__(256) void k_cvt(const float* __restrict__ Wi,
        const float* __restrict__ Wu, const float* __restrict__ Wo,
        const float* __restrict__ W1, const float* __restrict__ W2) {
    int i = blockIdx.x * 256 + threadIdx.x;          // 65536 threads
    {   // ffn1 [128k,512n] -> [512n,128k]
        int nn = i >> 7, kk = i & 127;
        float v = W1[(size_t)kk * FFN + nn];
        g_w1h[i] = __float2bfloat16(v);
        g_w1l[i] = __float2bfloat16(v - bf_hi(v));
    }
    {   // ffn2 [512k,128n] -> [128n,512k]
        int nn = i >> 9, kk = i & 511;
        float v = W2[(size_t)kk * DIM + nn];
        g_w2h[i] = __float2bfloat16(v);
        g_w2l[i] = __float2bfloat16(v - bf_hi(v));
    }
    if (i < DIM * DIM) {    // W_in [128k,128n] -> [128n,128k]
        int nn = i >> 7, kk = i & 127;
        float v = Wi[(size_t)kk * DIM + nn];
        g_wih[i] = __float2bfloat16(v);
        g_wil[i] = __float2bfloat16(v - bf_hi(v));
    }
    if (i < DIM * DIM) {    // W_out
        int nn = i >> 7, kk = i & 127;
        float v = Wo[(size_t)kk * DIM + nn];
        g_woh[i] = __float2bfloat16(v);
        g_wol[i] = __float2bfloat16(v - bf_hi(v));
    }
    if (i < DIM * 256) {    // W_upd [256k,128n] -> [128n,256k]
        int kk = i >> 7, nn = i & 127;
        float v = Wu[(size_t)kk * DIM + nn];
        g_wuh[nn * 256 + kk] = __float2bfloat16(v);
        g_wul[nn * 256 + kk] = __float2bfloat16(v - bf_hi(v));
    }
}

// ====================== Kernel A: h = x @ W_in + b  (HMMA) ================
__global__ __launch_bounds__(TPB, 2) void k_win(const float* __restrict__ x,
        const float* __restrict__ b, int n) {
    extern __shared__ __nv_bfloat16 smb[];
    __nv_bfloat16* Ah = smb;
    __nv_bfloat16* Al = smb + ASZ;
    __nv_bfloat16* Bh = smb + 2 * ASZ;
    __nv_bfloat16* Bl = smb + 2 * ASZ + BSZ;
    const int tid = threadIdx.x, wid = tid >> 5, lane = tid & 31;
    const int row0 = blockIdx.x * RT;
    stage_t(s2u(Bh), g_wih, DIM, 0, 0, 128, 128, tid);
    stage_t(s2u(Bl), g_wil, DIM, 0, 0, 128, 128, tid);
    stage_s(Ah, Al, x, DIM, row0, RT, n, tid);
    cpa_wait();
    __syncthreads();
    const int mw = (wid & 1) * 32, nw = (wid >> 1) * 32;
    float C[2][4][4];
    C_ZERO(C)
    mma_split(s2u(Ah), s2u(Al), s2u(Bh), s2u(Bl), lane, mw, nw, C);
    const int rL = lane >> 2, cL = (lane & 3) * 2;
    #pragma unroll
    for (int ni = 0; ni < 4; ni++) {
        int c = nw + ni * 8 + cL;
        float bb0 = __ldg(b + c), bb1 = __ldg(b + c + 1);
        #pragma unroll
        for (int mi = 0; mi < 2; mi++) {
            #pragma unroll
            for (int h = 0; h < 2; h++) {
                int row = row0 + mw + mi * 16 + h * 8 + rL;
                if (row < n) {
                    float v0 = C[mi][ni][h * 2]     + bb0;
                    float v1 = C[mi][ni][h * 2 + 1] + bb1;
                    *(float2*)(g_h + (size_t)row * DIM + c) = make_float2(v0, v1);
                    *(uint32_t*)((uint16_t*)g_hh + (size_t)row * DIM + c) = pbf(v0, v1);
                    *(uint32_t*)((uint16_t*)g_hl + (size_t)row * DIM + c) =
                        pbf(v0 - bf_hi(v0), v1 - bf_hi(v1));
                }
            }
        }
    }
}

// ====================== Kernel B1: h2 = [h|md] @ W_upd + bu  (HMMA) =======
__global__ __launch_bounds__(TPB, 2) void k_msg1(const void* __restrict__ eidx,
        const float* __restrict__ bu, int n) {
    extern __shared__ __nv_bfloat16 smb[];
    __nv_bfloat16* Ah = smb;
    __nv_bfloat16* Al = smb + ASZ;
    __nv_bfloat16* Bh = smb + 2 * ASZ;
    __nv_bfloat16* Bl = smb + 2 * ASZ + BSZ;
    int* srcb = (int*)(smb + 2 * ASZ + 2 * BSZ);
    int* flag = srcb + RT * KNN;
    const int tid = threadIdx.x, wid = tid >> 5, lane = tid & 31;
    const int row0 = blockIdx.x * RT;
    if (tid == 0) {
        const long long* p64 = (const long long*)eidx;
        int ok = 1;
        #pragma unroll
        for (int i = 0; i < 16; i++) {
            long long v = p64[i];
            if (v < 0 || v >= (long long)n) ok = 0;
        }
        *flag = ok;
    }
    // chunk-0 staging (async) before the srcb barrier
    stage_t(s2u(Ah), g_hh, DIM, 0, row0, RT, n, tid);
    stage_t(s2u(Al), g_hl, DIM, 0, row0, RT, n, tid);
    stage_t(s2u(Bh), g_wuh, 256, 0, 0, 128, 128, tid);
    stage_t(s2u(Bl), g_wul, 256, 0, 0, 128, 128, tid);
    __syncthreads();
    const int is64 = *flag;
    for (int i = tid; i < RT * KNN; i += TPB) {
        int r = i / KNN;
        int row = row0 + r;
        int s = 0;
        if (row < n) {
            size_t e = (size_t)row * KNN + (i - r * KNN);
            long long v = is64 ? ((const long long*)eidx)[e]
                               : (long long)((const int*)eidx)[e];
            s = (int)v;
            s = min(max(s, 0), n - 1);
        }
        srcb[i] = s;
    }
    const int mw = (wid & 1) * 32, nw = (wid >> 1) * 32;
    float C[2][4][4];
    C_ZERO(C)
    uint32_t sAh = s2u(Ah), sAl = s2u(Al), sBh = s2u(Bh), sBl = s2u(Bl);
    cpa_wait();
    __syncthreads();
    mma_split(sAh, sAl, sBh, sBl, lane, mw, nw, C);
    __syncthreads();
    // chunk 1: maxdiff half (gather + split in-register) + W_upd rows 128..255
    stage_t(sBh, g_wuh, 256, 128, 0, 128, 128, tid);
    stage_t(sBl, g_wul, 256, 128, 0, 128, 128, tid);
    #pragma unroll 1
    for (int i = tid; i < RT * 16; i += TPB) {
        int r = i >> 4, ch = i & 15;
        int d0 = ch * 8;
        int row = row0 + r;
        float4 mA = make_float4(-3.4e38f, -3.4e38f, -3.4e38f, -3.4e38f);
        float4 mB = mA;
        const int* sp = srcb + r * KNN;
        #pragma unroll
        for (int j = 0; j < KNN; j++) {
            const float* hp = g_h + (size_t)sp[j] * DIM + d0;
            float4 a = *(const float4*)hp;
            float4 bq = *(const float4*)(hp + 4);
            mA.x = fmaxf(mA.x, a.x);  mA.y = fmaxf(mA.y, a.y);
            mA.z = fmaxf(mA.z, a.z);  mA.w = fmaxf(mA.w, a.w);
            mB.x = fmaxf(mB.x, bq.x); mB.y = fmaxf(mB.y, bq.y);
            mB.z = fmaxf(mB.z, bq.z); mB.w = fmaxf(mB.w, bq.w);
        }
        float4 o0 = make_float4(0.f, 0.f, 0.f, 0.f), o1 = o0;
        if (row < n) {
            const float* op = g_h + (size_t)row * DIM + d0;
            float4 a = *(const float4*)op;
            float4 bq = *(const float4*)(op + 4);
            o0.x = mA.x - a.x;  o0.y = mA.y - a.y;
            o0.z = mA.z - a.z;  o0.w = mA.w - a.w;
            o1.x = mB.x - bq.x; o1.y = mB.y - bq.y;
            o1.z = mB.z - bq.z; o1.w = mB.w - bq.w;
        }
        uint4 hh, ll;
        hh.x = pbf(o0.x, o0.y); hh.y = pbf(o0.z, o0.w);
        hh.z = pbf(o1.x, o1.y); hh.w = pbf(o1.z, o1.w);
        ll.x = pbf(o0.x - bf_hi(o0.x), o0.y - bf_hi(o0.y));
        ll.y = pbf(o0.z - bf_hi(o0.z), o0.w - bf_hi(o0.w));
        ll.z = pbf(o1.x - bf_hi(o1.x), o1.y - bf_hi(o1.y));
        ll.w = pbf(o1.z - bf_hi(o1.z), o1.w - bf_hi(o1.w));
        *(uint4*)(Ah + r * SA + ch * 8) = hh;
        *(uint4*)(Al + r * SA + ch * 8) = ll;
    }
    cpa_wait();
    __syncthreads();
    mma_split(sAh, sAl, sBh, sBl, lane, mw, nw, C);
    const int rL = lane >> 2, cL = (lane & 3) * 2;
    #pragma unroll
    for (int ni = 0; ni < 4; ni++) {
        int c = nw + ni * 8 + cL;
        float bb0 = __ldg(bu + c), bb1 = __ldg(bu + c + 1);
        #pragma unroll
        for (int mi = 0; mi < 2; mi++) {
            #pragma unroll
            for (int h = 0; h < 2; h++) {
                int row = row0 + mw + mi * 16 + h * 8 + rL;
                if (row < n) {
                    float v0 = C[mi][ni][h * 2]     + bb0;
                    float v1 = C[mi][ni][h * 2 + 1] + bb1;
                    *(uint32_t*)((uint16_t*)g_h2h + (size_t)row * DIM + c) = pbf(v0, v1);
                    *(uint32_t*)((uint16_t*)g_h2l + (size_t)row * DIM + c) =
                        pbf(v0 - bf_hi(v0), v1 - bf_hi(v1));
                }
            }
        }
    }
}

// ====================== Kernel B2: W_out + LN1  (HMMA) ====================
__global__ __launch_bounds__(TPB, 2) void k_msg2(const float* __restrict__ x,
        const float* __restrict__ bo, const float* __restrict__ g1,
        const float* __restrict__ b1, int n) {
    extern __shared__ __nv_bfloat16 smb[];
    __nv_bfloat16* Ah = smb;
    __nv_bfloat16* Al = smb + ASZ;
    __nv_bfloat16* Bh = smb + 2 * ASZ;
    __nv_bfloat16* Bl = smb + 2 * ASZ + BSZ;
    const int tid = threadIdx.x, wid = tid >> 5, lane = tid & 31;
    const int row0 = blockIdx.x * RT;
    stage_t(s2u(Ah), g_h2h, DIM, 0, row0, RT, n, tid);
    stage_t(s2u(Al), g_h2l, DIM, 0, row0, RT, n, tid);
    stage_t(s2u(Bh), g_woh, DIM, 0, 0, 128, 128, tid);
    stage_t(s2u(Bl), g_wol, DIM, 0, 0, 128, 128, tid);
    cpa_wait();
    __syncthreads();
    const int mw = (wid & 1) * 32, nw = (wid >> 1) * 32;
    float C[2][4][4];
    C_ZERO(C)
    mma_split(s2u(Ah), s2u(Al), s2u(Bh), s2u(Bl), lane, mw, nw, C);
    __syncthreads();                 // MMA reads done; reuse smem as resid
    float* resid = (float*)smb;      // RT x RSTR floats
    const int rL = lane >> 2, cL = (lane & 3) * 2;
    #pragma unroll
    for (int ni = 0; ni < 4; ni++) {
        int c = nw + ni * 8 + cL;
        float bb0 = __ldg(bo + c), bb1 = __ldg(bo + c + 1);
        #pragma unroll
        for (int mi = 0; mi < 2; mi++) {
            #pragma unroll
            for (int h = 0; h < 2; h++) {
                int rl = mw + mi * 16 + h * 8 + rL;
                int row = row0 + rl;
                float2 xv = make_float2(0.f, 0.f);
                if (row < n) xv = *(const float2*)(x + (size_t)row * DIM + c);
                resid[rl * RSTR + c    ] = C[mi][ni][h * 2]     + bb0 + xv.x;
                resid[rl * RSTR + c + 1] = C[mi][ni][h * 2 + 1] + bb1 + xv.y;
            }
        }
    }
    __syncthreads();
    ln_rows_emit(resid, RSTR, g1, b1, g_x1, g_x1h, g_x1l, row0, n, tid);
}

// ====================== Kernel C: ffn1 (HMMA) =============================
__global__ __launch_bounds__(TPB, 2) void k_ffn1(const float* __restrict__ b1, int n) {
    extern __shared__ __nv_bfloat16 smb[];
    __nv_bfloat16* Ah = smb;
    __nv_bfloat16* Al = smb + ASZ;
    __nv_bfloat16* Bh = smb + 2 * ASZ;
    __nv_bfloat16* Bl = smb + 2 * ASZ + BSZ;
    const int tid = threadIdx.x, wid = tid >> 5, lane = tid & 31;
    const int row0 = blockIdx.x * RT;
    const int colbase = blockIdx.y * 128;
    stage_t(s2u(Ah), g_x1h, DIM, 0, row0, RT, n, tid);
    stage_t(s2u(Al), g_x1l, DIM, 0, row0, RT, n, tid);
    stage_t(s2u(Bh), g_w1h, DIM, 0, colbase, 128, 1 << 30, tid);
    stage_t(s2u(Bl), g_w1l, DIM, 0, colbase, 128, 1 << 30, tid);
    cpa_wait();
    __syncthreads();
    const int mw = (wid & 1) * 32, nw = (wid >> 1) * 32;
    float C[2][4][4];
    C_ZERO(C)
    mma_split(s2u(Ah), s2u(Al), s2u(Bh), s2u(Bl), lane, mw, nw, C);
    const int rL = lane >> 2, cL = (lane & 3) * 2;
    #pragma unroll
    for (int ni = 0; ni < 4; ni++) {
        int c = colbase + nw + ni * 8 + cL;
        float bb0 = __ldg(b1 + c), bb1 = __ldg(b1 + c + 1);
        #pragma unroll
        for (int mi = 0; mi < 2; mi++) {
            #pragma unroll
            for (int h = 0; h < 2; h++) {
                int row = row0 + mw + mi * 16 + h * 8 + rL;
                if (row < n) {
                    float v0 = gelu_exact(C[mi][ni][h * 2]     + bb0);
                    float v1 = gelu_exact(C[mi][ni][h * 2 + 1] + bb1);
                    *(uint32_t*)((uint16_t*)g_th + (size_t)row * FFN + c) = pbf(v0, v1);
                    *(uint32_t*)((uint16_t*)g_tl + (size_t)row * FFN + c) =
                        pbf(v0 - bf_hi(v0), v1 - bf_hi(v1));
                }
            }
        }
    }
}

// ====================== Kernel D: ffn2 + LN2 (HMMA) =======================
__global__ __launch_bounds__(TPB, 2) void k_ffn2(const float* __restrict__ b2,
        const float* __restrict__ g2, const float* __restrict__ bl,
        float* __restrict__ out, int n) {
    extern __shared__ __nv_bfloat16 smb[];
    __nv_bfloat16* Ah = smb;
    __nv_bfloat16* Al = smb + ASZ;
    __nv_bfloat16* Bh = smb + 2 * ASZ;
    __nv_bfloat16* Bl = smb + 2 * ASZ + BSZ;
    const int tid = threadIdx.x, wid = tid >> 5, lane = tid & 31;
    const int row0 = blockIdx.x * RT;
    const int mw = (wid & 1) * 32, nw = (wid >> 1) * 32;
    float C[2][4][4];
    C_ZERO(C)
    uint32_t sAh = s2u(Ah), sAl = s2u(Al), sBh = s2u(Bh), sBl = s2u(Bl);
    #pragma unroll 1
    for (int kc = 0; kc < 4; kc++) {
        stage_t(sAh, g_th,  FFN, kc * 128, row0, RT, n, tid);
        stage_t(sAl, g_tl,  FFN, kc * 128, row0, RT, n, tid);
        stage_t(sBh, g_w2h, FFN, kc * 128, 0, 128, 128, tid);
        stage_t(sBl, g_w2l, FFN, kc * 128, 0, 128, 128, tid);
        cpa_wait();
        __syncthreads();
        mma_split(sAh, sAl, sBh, sBl, lane, mw, nw, C);
        __syncthreads();
    }
    float* resid = (float*)smb;
    const int rL = lane >> 2, cL = (lane & 3) * 2;
    #pragma unroll
    for (int ni = 0; ni < 4; ni++) {
        int c = nw + ni * 8 + cL;
        float bb0 = __ldg(b2 + c), bb1 = __ldg(b2 + c + 1);
        #pragma unroll
        for (int mi = 0; mi < 2; mi++) {
            #pragma unroll
            for (int h = 0; h < 2; h++) {
                int rl = mw + mi * 16 + h * 8 + rL;
                int row = row0 + rl;
                float2 xv = make_float2(0.f, 0.f);
                if (row < n) xv = *(const float2*)(g_x1 + (size_t)row * DIM + c);
                resid[rl * RSTR + c    ] = C[mi][ni][h * 2]     + bb0 + xv.x;
                resid[rl * RSTR + c + 1] = C[mi][ni][h * 2 + 1] + bb1 + xv.y;
            }
        }
    }
    __syncthreads();
    {
        const int d = lane * 4;
        float4 gv = *(const float4*)(g2 + d);
        float4 bv = *(const float4*)(bl + d);
        for (int rl = wid; rl < RT; rl += 8) {
            int row = row0 + rl;
            if (row >= n) continue;
            float4 v = *(const float4*)(resid + rl * RSTR + d);
            float s  = v.x + v.y + v.z + v.w;
            float sq = v.x * v.x + v.y * v.y + v.z * v.z + v.w * v.w;
            #pragma unroll
            for (int m = 16; m; m >>= 1) {
                s  += __shfl_xor_sync(0xffffffffu, s,  m);
                sq += __shfl_xor_sync(0xffffffffu, sq, m);
            }
            float mu = s * (1.f / DIM);
            float var = sq * (1.f / DIM) - mu * mu;
            float rs = rsqrtf(var + 1e-5f);
            float4 o;
            o.x = (v.x - mu) * rs * gv.x + bv.x;
            o.y = (v.y - mu) * rs * gv.y + bv.y;
            o.z = (v.z - mu) * rs * gv.z + bv.z;
            o.w = (v.w - mu) * rs * gv.w + bv.w;
            *(float4*)&out[(size_t)row * DIM + d] = o;
        }
    }
}

// =====================================================================
extern "C" void kernel_launch(void* const* d_in, const int* in_sizes, int n_in,
                              void* d_out, int out_size) {
    const float* x    = (const float*)d_in[0];
    const void*  ei   = (const void*)d_in[1];
    const float* Winw = (const float*)d_in[2];
    const float* Winb = (const float*)d_in[3];
    const float* Wupw = (const float*)d_in[4];
    const float* Wupb = (const float*)d_in[5];
    const float* Wouw = (const float*)d_in[6];
    const float* Woub = (const float*)d_in[7];
    const float* ln1g = (const float*)d_in[8];
    const float* ln1b = (const float*)d_in[9];
    const float* ln2g = (const float*)d_in[10];
    const float* ln2b = (const float*)d_in[11];
    const float* f1w  = (const float*)d_in[12];
    const float* f1b  = (const float*)d_in[13];
    const float* f2w  = (const float*)d_in[14];
    const float* f2b  = (const float*)d_in[15];
    float* out = (float*)d_out;

    const int n = in_sizes[0] / DIM;

    cudaFuncSetAttribute(k_win,  cudaFuncAttributeMaxDynamicSharedMemorySize, FS_BYTES);
    cudaFuncSetAttribute(k_msg1, cudaFuncAttributeMaxDynamicSharedMemorySize, MSG1_BYTES);
    cudaFuncSetAttribute(k_msg2, cudaFuncAttributeMaxDynamicSharedMemorySize, FS_BYTES);
    cudaFuncSetAttribute(k_ffn1, cudaFuncAttributeMaxDynamicSharedMemorySize, FS_BYTES);
    cudaFuncSetAttribute(k_ffn2, cudaFuncAttributeMaxDynamicSharedMemorySize, FS_BYTES);

    const int nb = (n + RT - 1) / RT;
    dim3 gc(nb, 4);

    k_cvt <<<256, 256>>>(Winw, Wupw, Wouw, f1w, f2w);
    k_win <<<nb, TPB, FS_BYTES>>>(x, Winb, n);
    k_msg1<<<nb, TPB, MSG1_BYTES>>>(ei, Wupb, n);
    k_msg2<<<nb, TPB, FS_BYTES>>>(x, Woub, ln1g, ln1b, n);
    k_ffn1<<<gc, TPB, FS_BYTES>>>(f1b, n);
    k_ffn2<<<nb, TPB, FS_BYTES>>>(f2b, ln2g, ln2b, out, n);
}

// round 15
// speedup vs baseline: 1.0619x; 1.0619x over previous
#include <cuda_runtime.h>
#include <cuda_bf16.h>
#include <cstdint>
#include <math.h>

#define DIM 128
#define FFN 512
#define KNN 9
#define TPB 256
#define RT  128      // rows per CTA tile (M)
#define NMAX 50000

#define SA 136       // full-K tile row stride (elems): 128+8, conflict-free ldmatrix
#define SK 72        // K=64-chunk tile row stride (elems): 64+8, conflict-free
#define RSTR 132     // resid smem row stride (floats)
#define TA (128 * SA)            // full-K tile elems (17408)
#define TK (128 * SK)            // K64 tile elems (9216)
#define FS_BYTES (4 * TA * 2)                          // 139264 (win)
#define MSG1_BYTES (FS_BYTES + (RT * KNN + 2) * 4)
#define PIPE_BYTES (8 * TK * 2)                        // 147456 (msg2/ffn2: 2 stages x 4 tiles)
#define FFN1_BYTES (6 * TA * 2)                        // 208896 (A pair + 2-stage B pair)

// ====================== scalar helpers ====================================
__device__ __forceinline__ float gelu_exact(float v) {
    return 0.5f * v * (1.0f + erff(v * 0.70710678118654752f));
}
__device__ __forceinline__ uint32_t pbf(float a, float b) {
    uint16_t ua = __bfloat16_as_ushort(__float2bfloat16(a));
    uint16_t ub = __bfloat16_as_ushort(__float2bfloat16(b));
    return (uint32_t)ua | ((uint32_t)ub << 16);
}
__device__ __forceinline__ float bf_hi(float v) {
    return __bfloat162float(__float2bfloat16(v));
}

// ====================== HMMA / cp.async helpers (compute_100-safe) ========
__device__ __forceinline__ uint32_t s2u(const void* p) {
    uint32_t a;
    asm("{ .reg .u64 t; cvta.to.shared.u64 t, %1; cvt.u32.u64 %0, t; }"
        : "=r"(a) : "l"(p));
    return a;
}
__device__ __forceinline__ void ldsm4(uint32_t* r, uint32_t addr) {
    asm volatile("ldmatrix.sync.aligned.m8n8.x4.shared.b16 {%0,%1,%2,%3}, [%4];"
        : "=r"(r[0]), "=r"(r[1]), "=r"(r[2]), "=r"(r[3]) : "r"(addr));
}
__device__ __forceinline__ void mma_bf16(float* c, const uint32_t* a,
                                         uint32_t b0, uint32_t b1) {
    asm volatile(
        "mma.sync.aligned.m16n8k16.row.col.f32.bf16.bf16.f32 "
        "{%0,%1,%2,%3}, {%4,%5,%6,%7}, {%8,%9}, {%0,%1,%2,%3};"
        : "+f"(c[0]), "+f"(c[1]), "+f"(c[2]), "+f"(c[3])
        : "r"(a[0]), "r"(a[1]), "r"(a[2]), "r"(a[3]), "r"(b0), "r"(b1));
}
__device__ __forceinline__ void cpa16(uint32_t dst, const void* src, int srcsz) {
    asm volatile("cp.async.cg.shared.global [%0], [%1], 16, %2;"
        :: "r"(dst), "l"(src), "r"(srcsz));
}
__device__ __forceinline__ void cpa_commit() {
    asm volatile("cp.async.commit_group;" ::: "memory");
}
__device__ __forceinline__ void cpa_wait0() {
    asm volatile("cp.async.wait_group 0;" ::: "memory");
}

// ====================== scratch (no allocations anywhere) =================
__device__ float g_h [(size_t)NMAX * DIM];
__device__ float g_x1[(size_t)NMAX * DIM];
__device__ __align__(256) __nv_bfloat16 g_hh [(size_t)NMAX * DIM];
__device__ __align__(256) __nv_bfloat16 g_hl [(size_t)NMAX * DIM];
__device__ __align__(256) __nv_bfloat16 g_h2h[(size_t)NMAX * DIM];
__device__ __align__(256) __nv_bfloat16 g_h2l[(size_t)NMAX * DIM];
__device__ __align__(256) __nv_bfloat16 g_x1h[(size_t)NMAX * DIM];
__device__ __align__(256) __nv_bfloat16 g_x1l[(size_t)NMAX * DIM];
__device__ __align__(256) __nv_bfloat16 g_th [(size_t)NMAX * FFN];
__device__ __align__(256) __nv_bfloat16 g_tl [(size_t)NMAX * FFN];
__device__ __align__(256) __nv_bfloat16 g_wih[DIM * DIM], g_wil[DIM * DIM];   // W_in^T  [128n,128k]
__device__ __align__(256) __nv_bfloat16 g_wuh[DIM * 256], g_wul[DIM * 256];   // W_upd^T [128n,256k]
__device__ __align__(256) __nv_bfloat16 g_woh[DIM * DIM], g_wol[DIM * DIM];   // W_out^T [128n,128k]
__device__ __align__(256) __nv_bfloat16 g_w1h[FFN * DIM], g_w1l[FFN * DIM];   // ffn1^T  [512n,128k]
__device__ __align__(256) __nv_bfloat16 g_w2h[DIM * FFN], g_w2l[DIM * FFN];   // ffn2^T  [128n,512k]

// ====================== staging ===========================================
// bf16 src -> smem tile (register path, 128 rows x 128 k, stride SA)
__device__ __forceinline__ void stage_r(__nv_bfloat16* dst,
        const __nv_bfloat16* __restrict__ src, int ldk, int k0,
        int row0, int nvalid, int tid) {
    #pragma unroll
    for (int p = 0; p < 8; p++) {
        int i = tid + p * TPB;
        int row = i >> 4, ch = i & 15;
        uint4 v = make_uint4(0u, 0u, 0u, 0u);
        int gr = row0 + row;
        if (gr < nvalid)
            v = *(const uint4*)(src + (size_t)gr * ldk + k0 + ch * 8);
        *(uint4*)(dst + row * SA + ch * 8) = v;
    }
}
// bf16 src -> smem via cp.async; NCH 16B-chunks per row, stride ST elems
template<int NCH, int ST>
__device__ __forceinline__ void stage_c(uint32_t dst,
        const __nv_bfloat16* __restrict__ src, int ldk, int k0,
        int row0, int nvalid, int tid) {
    #pragma unroll
    for (int i = tid; i < 128 * NCH; i += TPB) {
        int row = i / NCH, ch = i % NCH;
        int gr = row0 + row;
        int sz = (gr < nvalid) ? 16 : 0;
        int gs = min(gr, nvalid - 1);
        cpa16(dst + (uint32_t)((row * ST + ch * 8) * 2),
              src + (size_t)gs * ldk + k0 + ch * 8, sz);
    }
}
// fp32 src -> split hi/lo smem tiles (register path, stride SA)
__device__ __forceinline__ void stage_s(__nv_bfloat16* Ah, __nv_bfloat16* Al,
        const float* __restrict__ src, int ldk, int row0, int nvalid, int tid) {
    #pragma unroll
    for (int p = 0; p < 8; p++) {
        int i = tid + p * TPB;
        int row = i >> 4, ch = i & 15;
        float4 v0 = make_float4(0.f, 0.f, 0.f, 0.f), v1 = v0;
        int gr = row0 + row;
        if (gr < nvalid) {
            const float* s = src + (size_t)gr * ldk + ch * 8;
            v0 = *(const float4*)s;
            v1 = *(const float4*)(s + 4);
        }
        uint4 hh, ll;
        hh.x = pbf(v0.x, v0.y); hh.y = pbf(v0.z, v0.w);
        hh.z = pbf(v1.x, v1.y); hh.w = pbf(v1.z, v1.w);
        ll.x = pbf(v0.x - bf_hi(v0.x), v0.y - bf_hi(v0.y));
        ll.y = pbf(v0.z - bf_hi(v0.z), v0.w - bf_hi(v0.w));
        ll.z = pbf(v1.x - bf_hi(v1.x), v1.y - bf_hi(v1.y));
        ll.w = pbf(v1.z - bf_hi(v1.z), v1.w - bf_hi(v1.w));
        *(uint4*)(Ah + row * SA + ch * 8) = hh;
        *(uint4*)(Al + row * SA + ch * 8) = ll;
    }
}

// ====================== core warp-tile MMA (32x64 slice) ==================
template<int KS, int ST>
__device__ __forceinline__ void mma_tile(uint32_t sA, uint32_t sB,
        int lane, int mw, int nw, float C[2][8][4]) {
    uint32_t aB = sA + (uint32_t)(((mw + (lane & 15)) * ST + (lane >> 4) * 8) * 2);
    uint32_t bB = sB + (uint32_t)(((nw + ((lane >> 4) << 3) + (lane & 7)) * ST
                                   + (((lane >> 3) & 1) << 3)) * 2);
    #pragma unroll
    for (int k = 0; k < KS; k++) {
        uint32_t a0[4], a1[4];
        ldsm4(a0, aB + k * 32);
        ldsm4(a1, aB + 16 * ST * 2 + k * 32);
        #pragma unroll
        for (int nj = 0; nj < 4; nj++) {
            uint32_t b[4];
            ldsm4(b, bB + nj * (16 * ST * 2) + k * 32);
            mma_bf16(C[0][nj * 2],     a0, b[0], b[1]);
            mma_bf16(C[0][nj * 2 + 1], a0, b[2], b[3]);
            mma_bf16(C[1][nj * 2],     a1, b[0], b[1]);
            mma_bf16(C[1][nj * 2 + 1], a1, b[2], b[3]);
        }
    }
}
#define C_ZERO(C)                                   \
    _Pragma("unroll")                               \
    for (int a_ = 0; a_ < 2; a_++)                  \
        _Pragma("unroll")                           \
        for (int b_ = 0; b_ < 8; b_++)              \
            _Pragma("unroll")                       \
            for (int c_ = 0; c_ < 4; c_++) C[a_][b_][c_] = 0.f;

template<int KS, int ST>
__device__ __forceinline__ void mma_split(uint32_t sAh, uint32_t sAl,
        uint32_t sBh, uint32_t sBl, int lane, int mw, int nw, float C[2][8][4]) {
    mma_tile<KS, ST>(sAh, sBh, lane, mw, nw, C);
    mma_tile<KS, ST>(sAh, sBl, lane, mw, nw, C);
    mma_tile<KS, ST>(sAl, sBh, lane, mw, nw, C);
}

// LN over RT rows of resid (stride rstr); emits fp32 + bf16 hi/lo split.
__device__ __forceinline__ void ln_rows_emit(const float* resid, int rstr,
        const float* __restrict__ gam, const float* __restrict__ bet,
        float* __restrict__ dstf, __nv_bfloat16* dsth, __nv_bfloat16* dstl,
        int row0, int n, int tid) {
    const int wid = tid >> 5, lane = tid & 31;
    const int d = lane * 4;
    float4 gv = *(const float4*)(gam + d);
    float4 bv = *(const float4*)(bet + d);
    for (int rl = wid; rl < RT; rl += 8) {
        int row = row0 + rl;
        if (row >= n) continue;
        float4 v = *(const float4*)(resid + rl * rstr + d);
        float s  = v.x + v.y + v.z + v.w;
        float sq = v.x * v.x + v.y * v.y + v.z * v.z + v.w * v.w;
        #pragma unroll
        for (int m = 16; m; m >>= 1) {
            s  += __shfl_xor_sync(0xffffffffu, s,  m);
            sq += __shfl_xor_sync(0xffffffffu, sq, m);
        }
        float mu = s * (1.f / DIM);
        float var = sq * (1.f / DIM) - mu * mu;
        float rs = rsqrtf(var + 1e-5f);
        float4 o;
        o.x = (v.x - mu) * rs * gv.x + bv.x;
        o.y = (v.y - mu) * rs * gv.y + bv.y;
        o.z = (v.z - mu) * rs * gv.z + bv.z;
        o.w = (v.w - mu) * rs * gv.w + bv.w;
        if (dstf) *(float4*)(dstf + (size_t)row * DIM + d) = o;
        uint2 hh, ll;
        hh.x = pbf(o.x, o.y);
        hh.y = pbf(o.z, o.w);
        ll.x = pbf(o.x - bf_hi(o.x), o.y - bf_hi(o.y));
        ll.y = pbf(o.z - bf_hi(o.z), o.w - bf_hi(o.w));
        *(uint2*)((uint16_t*)dsth + (size_t)row * DIM + d) = hh;
        *(uint2*)((uint16_t*)dstl + (size_t)row * DIM + d) = ll;
    }
}

// ====================== Kernel: weight convert/split ======================
__global__ __launch_bounds__(256) void k_cvt(const float* __restrict__ Wi,
        const float* __restrict__ Wu, const float* __restrict__ Wo,
        const float* __restrict__ W1, const float* __restrict__ W2) {
    int i = blockIdx.x * 256 + threadIdx.x;          // 65536 threads
    {   // ffn1 [128k,512n] -> [512n,128k]
        int nn = i >> 7, kk = i & 127;
        float v = W1[(size_t)kk * FFN + nn];
        g_w1h[i] = __float2bfloat16(v);
        g_w1l[i] = __float2bfloat16(v - bf_hi(v));
    }
    {   // ffn2 [512k,128n] -> [128n,512k]
        int nn = i >> 9, kk = i & 511;
        float v = W2[(size_t)kk * DIM + nn];
        g_w2h[i] = __float2bfloat16(v);
        g_w2l[i] = __float2bfloat16(v - bf_hi(v));
    }
    if (i < DIM * DIM) {    // W_in [128k,128n] -> [128n,128k]
        int nn = i >> 7, kk = i & 127;
        float v = Wi[(size_t)kk * DIM + nn];
        g_wih[i] = __float2bfloat16(v);
        g_wil[i] = __float2bfloat16(v - bf_hi(v));
    }
    if (i < DIM * DIM) {    // W_out
        int nn = i >> 7, kk = i & 127;
        float v = Wo[(size_t)kk * DIM + nn];
        g_woh[i] = __float2bfloat16(v);
        g_wol[i] = __float2bfloat16(v - bf_hi(v));
    }
    if (i < DIM * 256) {    // W_upd [256k,128n] -> [128n,256k]
        int kk = i >> 7, nn = i & 127;
        float v = Wu[(size_t)kk * DIM + nn];
        g_wuh[nn * 256 + kk] = __float2bfloat16(v);
        g_wul[nn * 256 + kk] = __float2bfloat16(v - bf_hi(v));
    }
}

// ====================== Kernel A: h = x @ W_in + b (round-13 form) ========
__global__ __launch_bounds__(TPB, 1) void k_win(const float* __restrict__ x,
        const float* __restrict__ b, int n) {
    extern __shared__ __nv_bfloat16 smb[];
    __nv_bfloat16* Ah = smb;
    __nv_bfloat16* Al = smb + TA;
    __nv_bfloat16* Bh = smb + 2 * TA;
    __nv_bfloat16* Bl = smb + 3 * TA;
    const int tid = threadIdx.x, wid = tid >> 5, lane = tid & 31;
    const int row0 = blockIdx.x * RT;
    stage_s(Ah, Al, x, DIM, row0, n, tid);
    stage_r(Bh, g_wih, DIM, 0, 0, 128, tid);
    stage_r(Bl, g_wil, DIM, 0, 0, 128, tid);
    __syncthreads();
    const int mw = (wid >> 1) * 32, nw = (wid & 1) * 64;
    float C[2][8][4];
    C_ZERO(C)
    mma_split<8, SA>(s2u(Ah), s2u(Al), s2u(Bh), s2u(Bl), lane, mw, nw, C);
    const int rL = lane >> 2, cL = (lane & 3) * 2;
    #pragma unroll
    for (int ni = 0; ni < 8; ni++) {
        int c = nw + ni * 8 + cL;
        float bb0 = __ldg(b + c), bb1 = __ldg(b + c + 1);
        #pragma unroll
        for (int mi = 0; mi < 2; mi++) {
            #pragma unroll
            for (int h = 0; h < 2; h++) {
                int row = row0 + mw + mi * 16 + h * 8 + rL;
                if (row < n) {
                    float v0 = C[mi][ni][h * 2]     + bb0;
                    float v1 = C[mi][ni][h * 2 + 1] + bb1;
                    *(float2*)(g_h + (size_t)row * DIM + c) = make_float2(v0, v1);
                    *(uint32_t*)((uint16_t*)g_hh + (size_t)row * DIM + c) = pbf(v0, v1);
                    *(uint32_t*)((uint16_t*)g_hl + (size_t)row * DIM + c) =
                        pbf(v0 - bf_hi(v0), v1 - bf_hi(v1));
                }
            }
        }
    }
}

// ====================== Kernel B1: h2 = [h|md] @ W_upd + bu (r13 form) ====
__global__ __launch_bounds__(TPB, 1) void k_msg1(const void* __restrict__ eidx,
        const float* __restrict__ bu, int n) {
    extern __shared__ __nv_bfloat16 smb[];
    __nv_bfloat16* Ah = smb;
    __nv_bfloat16* Al = smb + TA;
    __nv_bfloat16* Bh = smb + 2 * TA;
    __nv_bfloat16* Bl = smb + 3 * TA;
    int* srcb = (int*)(smb + 4 * TA);
    int* flag = srcb + RT * KNN;
    const int tid = threadIdx.x, wid = tid >> 5, lane = tid & 31;
    const int row0 = blockIdx.x * RT;
    if (tid == 0) {
        const long long* p64 = (const long long*)eidx;
        int ok = 1;
        #pragma unroll
        for (int i = 0; i < 16; i++) {
            long long v = p64[i];
            if (v < 0 || v >= (long long)n) ok = 0;
        }
        *flag = ok;
    }
    __syncthreads();
    const int is64 = *flag;
    for (int i = tid; i < RT * KNN; i += TPB) {
        int r = i / KNN;
        int row = row0 + r;
        int s = 0;
        if (row < n) {
            size_t e = (size_t)row * KNN + (i - r * KNN);
            long long v = is64 ? ((const long long*)eidx)[e]
                               : (long long)((const int*)eidx)[e];
            s = (int)v;
            s = min(max(s, 0), n - 1);
        }
        srcb[i] = s;
    }
    const int mw = (wid >> 1) * 32, nw = (wid & 1) * 64;
    float C[2][8][4];
    C_ZERO(C)
    uint32_t sAh = s2u(Ah), sAl = s2u(Al), sBh = s2u(Bh), sBl = s2u(Bl);
    stage_r(Ah, g_hh, DIM, 0, row0, n, tid);
    stage_r(Al, g_hl, DIM, 0, row0, n, tid);
    stage_r(Bh, g_wuh, 256, 0, 0, 128, tid);
    stage_r(Bl, g_wul, 256, 0, 0, 128, tid);
    __syncthreads();
    mma_split<8, SA>(sAh, sAl, sBh, sBl, lane, mw, nw, C);
    __syncthreads();
    #pragma unroll 1
    for (int i = tid; i < RT * 16; i += TPB) {
        int r = i >> 4, ch = i & 15;
        int d0 = ch * 8;
        int row = row0 + r;
        float4 mA = make_float4(-3.4e38f, -3.4e38f, -3.4e38f, -3.4e38f);
        float4 mB = mA;
        const int* sp = srcb + r * KNN;
        #pragma unroll
        for (int j = 0; j < KNN; j++) {
            const float* hp = g_h + (size_t)sp[j] * DIM + d0;
            float4 a = *(const float4*)hp;
            float4 bq = *(const float4*)(hp + 4);
            mA.x = fmaxf(mA.x, a.x);  mA.y = fmaxf(mA.y, a.y);
            mA.z = fmaxf(mA.z, a.z);  mA.w = fmaxf(mA.w, a.w);
            mB.x = fmaxf(mB.x, bq.x); mB.y = fmaxf(mB.y, bq.y);
            mB.z = fmaxf(mB.z, bq.z); mB.w = fmaxf(mB.w, bq.w);
        }
        float4 o0 = make_float4(0.f, 0.f, 0.f, 0.f), o1 = o0;
        if (row < n) {
            const float* op = g_h + (size_t)row * DIM + d0;
            float4 a = *(const float4*)op;
            float4 bq = *(const float4*)(op + 4);
            o0.x = mA.x - a.x;  o0.y = mA.y - a.y;
            o0.z = mA.z - a.z;  o0.w = mA.w - a.w;
            o1.x = mB.x - bq.x; o1.y = mB.y - bq.y;
            o1.z = mB.z - bq.z; o1.w = mB.w - bq.w;
        }
        uint4 hh, ll;
        hh.x = pbf(o0.x, o0.y); hh.y = pbf(o0.z, o0.w);
        hh.z = pbf(o1.x, o1.y); hh.w = pbf(o1.z, o1.w);
        ll.x = pbf(o0.x - bf_hi(o0.x), o0.y - bf_hi(o0.y));
        ll.y = pbf(o0.z - bf_hi(o0.z), o0.w - bf_hi(o0.w));
        ll.z = pbf(o1.x - bf_hi(o1.x), o1.y - bf_hi(o1.y));
        ll.w = pbf(o1.z - bf_hi(o1.z), o1.w - bf_hi(o1.w));
        *(uint4*)(Ah + r * SA + ch * 8) = hh;
        *(uint4*)(Al + r * SA + ch * 8) = ll;
    }
    stage_r(Bh, g_wuh, 256, 128, 0, 128, tid);
    stage_r(Bl, g_wul, 256, 128, 0, 128, tid);
    __syncthreads();
    mma_split<8, SA>(sAh, sAl, sBh, sBl, lane, mw, nw, C);
    const int rL = lane >> 2, cL = (lane & 3) * 2;
    #pragma unroll
    for (int ni = 0; ni < 8; ni++) {
        int c = nw + ni * 8 + cL;
        float bb0 = __ldg(bu + c), bb1 = __ldg(bu + c + 1);
        #pragma unroll
        for (int mi = 0; mi < 2; mi++) {
            #pragma unroll
            for (int h = 0; h < 2; h++) {
                int row = row0 + mw + mi * 16 + h * 8 + rL;
                if (row < n) {
                    float v0 = C[mi][ni][h * 2]     + bb0;
                    float v1 = C[mi][ni][h * 2 + 1] + bb1;
                    *(uint32_t*)((uint16_t*)g_h2h + (size_t)row * DIM + c) = pbf(v0, v1);
                    *(uint32_t*)((uint16_t*)g_h2l + (size_t)row * DIM + c) =
                        pbf(v0 - bf_hi(v0), v1 - bf_hi(v1));
                }
            }
        }
    }
}

// ====================== Kernel B2: W_out + LN1 (K64 ping-pong) ============
__global__ __launch_bounds__(TPB, 1) void k_msg2(const float* __restrict__ x,
        const float* __restrict__ bo, const float* __restrict__ g1,
        const float* __restrict__ b1, int n) {
    extern __shared__ __nv_bfloat16 smb[];
    const uint32_t sb = s2u(smb);
    const int tid = threadIdx.x, wid = tid >> 5, lane = tid & 31;
    const int row0 = blockIdx.x * RT;
    // stage st base: sb + st*4*TK*2 ; tiles: Ah,Al,Bh,Bl each TK elems
    #define BUF(st, idx) (sb + (uint32_t)(((st) * 4 + (idx)) * TK * 2))
    stage_c<8, SK>(BUF(0,0), g_h2h, DIM, 0, row0, n, tid);
    stage_c<8, SK>(BUF(0,1), g_h2l, DIM, 0, row0, n, tid);
    stage_c<8, SK>(BUF(0,2), g_woh, DIM, 0, 0, 128, tid);
    stage_c<8, SK>(BUF(0,3), g_wol, DIM, 0, 0, 128, tid);
    cpa_commit(); cpa_wait0();
    __syncthreads();
    const int mw = (wid >> 1) * 32, nw = (wid & 1) * 64;
    float C[2][8][4];
    C_ZERO(C)
    // chunk 0 compute overlapped with chunk 1 staging
    stage_c<8, SK>(BUF(1,0), g_h2h, DIM, 64, row0, n, tid);
    stage_c<8, SK>(BUF(1,1), g_h2l, DIM, 64, row0, n, tid);
    stage_c<8, SK>(BUF(1,2), g_woh, DIM, 64, 0, 128, tid);
    stage_c<8, SK>(BUF(1,3), g_wol, DIM, 64, 0, 128, tid);
    cpa_commit();
    mma_split<4, SK>(BUF(0,0), BUF(0,1), BUF(0,2), BUF(0,3), lane, mw, nw, C);
    cpa_wait0();
    __syncthreads();
    mma_split<4, SK>(BUF(1,0), BUF(1,1), BUF(1,2), BUF(1,3), lane, mw, nw, C);
    __syncthreads();                 // MMA reads done; reuse smem as resid
    float* resid = (float*)smb;
    const int rL = lane >> 2, cL = (lane & 3) * 2;
    #pragma unroll
    for (int ni = 0; ni < 8; ni++) {
        int c = nw + ni * 8 + cL;
        float bb0 = __ldg(bo + c), bb1 = __ldg(bo + c + 1);
        #pragma unroll
        for (int mi = 0; mi < 2; mi++) {
            #pragma unroll
            for (int h = 0; h < 2; h++) {
                int rl = mw + mi * 16 + h * 8 + rL;
                int row = row0 + rl;
                float2 xv = make_float2(0.f, 0.f);
                if (row < n) xv = *(const float2*)(x + (size_t)row * DIM + c);
                resid[rl * RSTR + c    ] = C[mi][ni][h * 2]     + bb0 + xv.x;
                resid[rl * RSTR + c + 1] = C[mi][ni][h * 2 + 1] + bb1 + xv.y;
            }
        }
    }
    __syncthreads();
    ln_rows_emit(resid, RSTR, g1, b1, g_x1, g_x1h, g_x1l, row0, n, tid);
    #undef BUF
}

// ====================== Kernel C: ffn1 (A once, B ping-pong over 2 slices)
__global__ __launch_bounds__(TPB, 1) void k_ffn1(const float* __restrict__ b1, int n) {
    extern __shared__ __nv_bfloat16 smb[];
    const uint32_t sb = s2u(smb);
    const int tid = threadIdx.x, wid = tid >> 5, lane = tid & 31;
    const int row0 = blockIdx.x * RT;
    const int ncb = blockIdx.y * 256;
    const uint32_t sAh = sb, sAl = sb + TA * 2;
    #define BBUF(st, hl) (sb + (uint32_t)((2 + (st) * 2 + (hl)) * TA * 2))
    stage_c<16, SA>(sAh, g_x1h, DIM, 0, row0, n, tid);
    stage_c<16, SA>(sAl, g_x1l, DIM, 0, row0, n, tid);
    stage_c<16, SA>(BBUF(0,0), g_w1h, DIM, 0, ncb, 1 << 30, tid);
    stage_c<16, SA>(BBUF(0,1), g_w1l, DIM, 0, ncb, 1 << 30, tid);
    cpa_commit(); cpa_wait0();
    __syncthreads();
    const int mw = (wid >> 1) * 32, nw = (wid & 1) * 64;
    const int rL = lane >> 2, cL = (lane & 3) * 2;
    #pragma unroll 1
    for (int s = 0; s < 2; s++) {
        if (s == 0) {
            stage_c<16, SA>(BBUF(1,0), g_w1h, DIM, 0, ncb + 128, 1 << 30, tid);
            stage_c<16, SA>(BBUF(1,1), g_w1l, DIM, 0, ncb + 128, 1 << 30, tid);
            cpa_commit();
        }
        float C[2][8][4];
        C_ZERO(C)
        mma_split<8, SA>(sAh, sAl, BBUF(s,0), BBUF(s,1), lane, mw, nw, C);
        const int colbase = ncb + s * 128;
        #pragma unroll
        for (int ni = 0; ni < 8; ni++) {
            int c = colbase + nw + ni * 8 + cL;
            float bb0 = __ldg(b1 + c), bb1 = __ldg(b1 + c + 1);
            #pragma unroll
            for (int mi = 0; mi < 2; mi++) {
                #pragma unroll
                for (int h = 0; h < 2; h++) {
                    int row = row0 + mw + mi * 16 + h * 8 + rL;
                    if (row < n) {
                        float v0 = gelu_exact(C[mi][ni][h * 2]     + bb0);
                        float v1 = gelu_exact(C[mi][ni][h * 2 + 1] + bb1);
                        *(uint32_t*)((uint16_t*)g_th + (size_t)row * FFN + c) = pbf(v0, v1);
                        *(uint32_t*)((uint16_t*)g_tl + (size_t)row * FFN + c) =
                            pbf(v0 - bf_hi(v0), v1 - bf_hi(v1));
                    }
                }
            }
        }
        if (s == 0) { cpa_wait0(); __syncthreads(); }
    }
    #undef BBUF
}

// ====================== Kernel D: ffn2 + LN2 (K64 x8 ping-pong) ===========
__global__ __launch_bounds__(TPB, 1) void k_ffn2(const float* __restrict__ b2,
        const float* __restrict__ g2, const float* __restrict__ bl,
        float* __restrict__ out, int n) {
    extern __shared__ __nv_bfloat16 smb[];
    const uint32_t sb = s2u(smb);
    const int tid = threadIdx.x, wid = tid >> 5, lane = tid & 31;
    const int row0 = blockIdx.x * RT;
    #define BUF(st, idx) (sb + (uint32_t)(((st) * 4 + (idx)) * TK * 2))
    stage_c<8, SK>(BUF(0,0), g_th,  FFN, 0, row0, n, tid);
    stage_c<8, SK>(BUF(0,1), g_tl,  FFN, 0, row0, n, tid);
    stage_c<8, SK>(BUF(0,2), g_w2h, FFN, 0, 0, 128, tid);
    stage_c<8, SK>(BUF(0,3), g_w2l, FFN, 0, 0, 128, tid);
    cpa_commit(); cpa_wait0();
    __syncthreads();
    const int mw = (wid >> 1) * 32, nw = (wid & 1) * 64;
    float C[2][8][4];
    C_ZERO(C)
    #pragma unroll 1
    for (int kc = 0; kc < 8; kc++) {
        int cur = kc & 1;
        if (kc < 7) {
            int nxt = cur ^ 1;
            int k0 = (kc + 1) * 64;
            stage_c<8, SK>(BUF(nxt,0), g_th,  FFN, k0, row0, n, tid);
            stage_c<8, SK>(BUF(nxt,1), g_tl,  FFN, k0, row0, n, tid);
            stage_c<8, SK>(BUF(nxt,2), g_w2h, FFN, k0, 0, 128, tid);
            stage_c<8, SK>(BUF(nxt,3), g_w2l, FFN, k0, 0, 128, tid);
            cpa_commit();
        }
        mma_split<4, SK>(BUF(cur,0), BUF(cur,1), BUF(cur,2), BUF(cur,3),
                         lane, mw, nw, C);
        if (kc < 7) { cpa_wait0(); __syncthreads(); }
    }
    __syncthreads();
    float* resid = (float*)smb;
    const int rL = lane >> 2, cL = (lane & 3) * 2;
    #pragma unroll
    for (int ni = 0; ni < 8; ni++) {
        int c = nw + ni * 8 + cL;
        float bb0 = __ldg(b2 + c), bb1 = __ldg(b2 + c + 1);
        #pragma unroll
        for (int mi = 0; mi < 2; mi++) {
            #pragma unroll
            for (int h = 0; h < 2; h++) {
                int rl = mw + mi * 16 + h * 8 + rL;
                int row = row0 + rl;
                float2 xv = make_float2(0.f, 0.f);
                if (row < n) xv = *(const float2*)(g_x1 + (size_t)row * DIM + c);
                resid[rl * RSTR + c    ] = C[mi][ni][h * 2]     + bb0 + xv.x;
                resid[rl * RSTR + c + 1] = C[mi][ni][h * 2 + 1] + bb1 + xv.y;
            }
        }
    }
    __syncthreads();
    {
        const int d = lane * 4;
        float4 gv = *(const float4*)(g2 + d);
        float4 bv = *(const float4*)(bl + d);
        for (int rl = wid; rl < RT; rl += 8) {
            int row = row0 + rl;
            if (row >= n) continue;
            float4 v = *(const float4*)(resid + rl * RSTR + d);
            float s  = v.x + v.y + v.z + v.w;
            float sq = v.x * v.x + v.y * v.y + v.z * v.z + v.w * v.w;
            #pragma unroll
            for (int m = 16; m; m >>= 1) {
                s  += __shfl_xor_sync(0xffffffffu, s,  m);
                sq += __shfl_xor_sync(0xffffffffu, sq, m);
            }
            float mu = s * (1.f / DIM);
            float var = sq * (1.f / DIM) - mu * mu;
            float rs = rsqrtf(var + 1e-5f);
            float4 o;
            o.x = (v.x - mu) * rs * gv.x + bv.x;
            o.y = (v.y - mu) * rs * gv.y + bv.y;
            o.z = (v.z - mu) * rs * gv.z + bv.z;
            o.w = (v.w - mu) * rs * gv.w + bv.w;
            *(float4*)&out[(size_t)row * DIM + d] = o;
        }
    }
    #undef BUF
}

// =====================================================================
extern "C" void kernel_launch(void* const* d_in, const int* in_sizes, int n_in,
                              void* d_out, int out_size) {
    const float* x    = (const float*)d_in[0];
    const void*  ei   = (const void*)d_in[1];
    const float* Winw = (const float*)d_in[2];
    const float* Winb = (const float*)d_in[3];
    const float* Wupw = (const float*)d_in[4];
    const float* Wupb = (const float*)d_in[5];
    const float* Wouw = (const float*)d_in[6];
    const float* Woub = (const float*)d_in[7];
    const float* ln1g = (const float*)d_in[8];
    const float* ln1b = (const float*)d_in[9];
    const float* ln2g = (const float*)d_in[10];
    const float* ln2b = (const float*)d_in[11];
    const float* f1w  = (const float*)d_in[12];
    const float* f1b  = (const float*)d_in[13];
    const float* f2w  = (const float*)d_in[14];
    const float* f2b  = (const float*)d_in[15];
    float* out = (float*)d_out;

    const int n = in_sizes[0] / DIM;

    cudaFuncSetAttribute(k_win,  cudaFuncAttributeMaxDynamicSharedMemorySize, FS_BYTES);
    cudaFuncSetAttribute(k_msg1, cudaFuncAttributeMaxDynamicSharedMemorySize, MSG1_BYTES);
    cudaFuncSetAttribute(k_msg2, cudaFuncAttributeMaxDynamicSharedMemorySize, PIPE_BYTES);
    cudaFuncSetAttribute(k_ffn1, cudaFuncAttributeMaxDynamicSharedMemorySize, FFN1_BYTES);
    cudaFuncSetAttribute(k_ffn2, cudaFuncAttributeMaxDynamicSharedMemorySize, PIPE_BYTES);

    const int nb = (n + RT - 1) / RT;
    dim3 gc(nb, 2);

    k_cvt <<<256, 256>>>(Winw, Wupw, Wouw, f1w, f2w);
    k_win <<<nb, TPB, FS_BYTES>>>(x, Winb, n);
    k_msg1<<<nb, TPB, MSG1_BYTES>>>(ei, Wupb, n);
    k_msg2<<<nb, TPB, PIPE_BYTES>>>(x, Woub, ln1g, ln1b, n);
    k_ffn1<<<gc, TPB, FFN1_BYTES>>>(f1b, n);
    k_ffn2<<<nb, TPB, PIPE_BYTES>>>(f2b, ln2g, ln2b, out, n);
}